// round 7
// baseline (speedup 1.0000x reference)
#include <cuda_runtime.h>
#include <cstdint>

// Depthwise causal FIR conv1d, K=31, fp32.
// x: (8, 4096, 2048) channel-last.  w: (2048, 31).  y like x.
//
// Round-7: register-window streaming (R3/R5 lineage) + taps in smem.
//  - thread = channel pair (float2), TT=128 outputs, CHUNK=8, full unroll
//  - 38-slot circular register window, static mod-38 indexing (zero MOVs)
//  - x: direct LDG.64 prefetch into window slots (8/chunk, ~1-chunk lead)
//  - taps: smem ws[31][64] float2 (conflict-free LDS.64, reused 16x/chunk)
//    -> frees 62 regs -> 8 blocks/SM (16 warps) instead of 6 (12)
//  - FFMA2 math (fma.rn.f32x2), bit-exact fp32

#define BB 8
#define LL 4096
#define CPAIR 1024
#define KK 31
#define CHUNK 8
#define TT 128
#define NCHUNK 16
#define WBUF 38          // 30 halo + 8 current
#define THREADS 64

__device__ __forceinline__ float2 ffma2(float2 a, float2 b, float2 c) {
    float2 d;
    asm("fma.rn.f32x2 %0, %1, %2, %3;"
        : "=l"(*reinterpret_cast<unsigned long long*>(&d))
        : "l"(*reinterpret_cast<const unsigned long long*>(&a)),
          "l"(*reinterpret_cast<const unsigned long long*>(&b)),
          "l"(*reinterpret_cast<const unsigned long long*>(&c)));
    return d;
}

__global__ __launch_bounds__(THREADS, 8)
void _DepthwiseFIRConv1d_kernel(const float* __restrict__ x,
                                const float* __restrict__ w,
                                float* __restrict__ y) {
    __shared__ float2 ws[KK][THREADS];                   // 15872 B

    const int tid = threadIdx.x;
    const int cp  = blockIdx.x * THREADS + tid;          // channel pair 0..1023
    const int l0  = blockIdx.y * TT;
    const int b   = blockIdx.z;

    const float2* xb = reinterpret_cast<const float2*>(x) + (size_t)b * LL * CPAIR + cp;
    float2*       yb = reinterpret_cast<float2*>(y) + ((size_t)b * LL + l0) * CPAIR + cp;
    const int base = l0 - (KK - 1);

    // Taps -> smem, transposed: ws[t][tid] = (w[c0][t], w[c1][t]).
    // 16 KB per block; L2-hot after the first wave.
    {
        const float* w0 = w + (2 * cp) * KK;
#pragma unroll
        for (int t = 0; t < KK; t++)
            ws[t][tid] = make_float2(__ldg(w0 + t), __ldg(w0 + KK + t));
    }
    __syncthreads();

    // Initial window: offsets 0..37 (chunk 0). Predicate only bites when l0==0.
    float2 buf[WBUF];
#pragma unroll
    for (int i = 0; i < WBUF; i++) {
        const int l = base + i;
        buf[i] = (l >= 0) ? xb[(size_t)l * CPAIR] : make_float2(0.0f, 0.0f);
    }

#pragma unroll
    for (int c = 0; c < NCHUNK; c++) {
        float2 acc[CHUNK];
#pragma unroll
        for (int j = 0; j < CHUNK; j++) acc[j] = make_float2(0.0f, 0.0f);

#pragma unroll
        for (int t = 0; t < KK; t++) {
            const float2 wt = ws[t][tid];                // LDS.64, feeds 8 FFMA2
#pragma unroll
            for (int j = 0; j < CHUNK; j++)
                acc[j] = ffma2(wt, buf[(CHUNK * c + j + t) % WBUF], acc[j]);
        }

#pragma unroll
        for (int j = 0; j < CHUNK; j++)
            yb[(size_t)(CHUNK * c + j) * CPAIR] = acc[j];

        // Prefetch offsets 8c+38 .. 8c+45 (top of chunk c+1's window) into the
        // slots chunk c just retired. l = l0 + 8c + 8 + i: always in [0, LL).
        if (c < NCHUNK - 1) {
#pragma unroll
            for (int i = 0; i < CHUNK; i++) {
                const int off = CHUNK * c + WBUF + i;
                buf[(CHUNK * c + i) % WBUF] = xb[(size_t)(base + off) * CPAIR];
            }
        }
    }
}

extern "C" void kernel_launch(void* const* d_in, const int* in_sizes, int n_in,
                              void* d_out, int out_size) {
    const float* x = (const float*)d_in[0];   // (8, 4096, 16, 128)
    const float* w = (const float*)d_in[1];   // (16, 128, 31)
    float* yv = (float*)d_out;

    dim3 grid(CPAIR / THREADS, LL / TT, BB);  // (16, 32, 8) = 4096 blocks
    _DepthwiseFIRConv1d_kernel<<<grid, THREADS>>>(x, w, yv);
}

// round 8
// speedup vs baseline: 2.6317x; 2.6317x over previous
#include <cuda_runtime.h>
#include <cstdint>

// Depthwise causal FIR conv1d, K=31, fp32.
// x: (8, 4096, 2048) channel-last.  w: (2048, 31).  y like x.
//
// Round-8: R5 register-window design, taps moved to smem with PINNED loads.
//  - thread = channel pair (float2), TT=128 outputs, CHUNK=8, full unroll
//  - 38-slot circular register window (static mod-38), direct LDG.64 prefetch
//  - taps: smem ws[31][64] (16 KB), read via asm-volatile ld.shared.v2.f32
//    into a 3-slot rotating buffer (3-tap lead) -> only 6 wt regs live,
//    ptxas cannot hoist/batch them (this is what spilled R7)
//  - NO reg cap: natural allocation ~112-124 -> 8 blocks = 16 warps/SM

#define BB 8
#define LL 4096
#define CPAIR 1024
#define KK 31
#define CHUNK 8
#define TT 128
#define NCHUNK 16
#define WBUF 38
#define THREADS 64

__device__ __forceinline__ float2 ffma2(float2 a, float2 b, float2 c) {
    float2 d;
    asm("fma.rn.f32x2 %0, %1, %2, %3;"
        : "=l"(*reinterpret_cast<unsigned long long*>(&d))
        : "l"(*reinterpret_cast<const unsigned long long*>(&a)),
          "l"(*reinterpret_cast<const unsigned long long*>(&b)),
          "l"(*reinterpret_cast<const unsigned long long*>(&c)));
    return d;
}

// Pinned LDS.64: volatile keeps ptxas from hoisting/batching weight loads.
__device__ __forceinline__ float2 lds_wt(uint32_t addr) {
    float2 v;
    asm volatile("ld.shared.v2.f32 {%0, %1}, [%2];"
                 : "=f"(v.x), "=f"(v.y) : "r"(addr));
    return v;
}

__global__ __launch_bounds__(THREADS)
void _DepthwiseFIRConv1d_kernel(const float* __restrict__ x,
                                const float* __restrict__ w,
                                float* __restrict__ y) {
    __shared__ float2 ws[KK][THREADS];                   // 15872 B

    const int tid = threadIdx.x;
    const int cpi = blockIdx.x * THREADS + tid;          // channel pair 0..1023
    const int l0  = blockIdx.y * TT;
    const int b   = blockIdx.z;

    const float2* xb = reinterpret_cast<const float2*>(x) + (size_t)b * LL * CPAIR + cpi;
    float2*       yb = reinterpret_cast<float2*>(y) + ((size_t)b * LL + l0) * CPAIR + cpi;
    const int base = l0 - (KK - 1);

    // Stage taps into smem: ws[t][tid] = (w[2cp][t], w[2cp+1][t]).
    {
        const float* w0 = w + (2 * cpi) * KK;
#pragma unroll
        for (int t = 0; t < KK; t++)
            ws[t][tid] = make_float2(__ldg(w0 + t), __ldg(w0 + KK + t));
    }
    __syncthreads();

    const uint32_t ws0 = (uint32_t)__cvta_generic_to_shared(&ws[0][tid]);
    // ws[t][tid] address = ws0 + t * (THREADS*8)

    // Initial window: offsets 0..37. Predicate only bites when l0==0.
    float2 buf[WBUF];
#pragma unroll
    for (int i = 0; i < WBUF; i++) {
        const int l = base + i;
        buf[i] = (l >= 0) ? xb[(size_t)l * CPAIR] : make_float2(0.0f, 0.0f);
    }

#pragma unroll
    for (int c = 0; c < NCHUNK; c++) {
        float2 acc[CHUNK];
#pragma unroll
        for (int j = 0; j < CHUNK; j++) acc[j] = make_float2(0.0f, 0.0f);

        // 3-slot rotating weight buffer, 3-tap lead (48 cyc > 29 cyc LDS lat).
        float2 wr[3];
        wr[0] = lds_wt(ws0 + 0 * (THREADS * 8));
        wr[1] = lds_wt(ws0 + 1 * (THREADS * 8));
        wr[2] = lds_wt(ws0 + 2 * (THREADS * 8));

#pragma unroll
        for (int t = 0; t < KK; t++) {
            const float2 wt = wr[t % 3];
#pragma unroll
            for (int j = 0; j < CHUNK; j++)
                acc[j] = ffma2(wt, buf[(CHUNK * c + j + t) % WBUF], acc[j]);
            if (t + 3 < KK)
                wr[t % 3] = lds_wt(ws0 + (uint32_t)(t + 3) * (THREADS * 8));
        }

#pragma unroll
        for (int j = 0; j < CHUNK; j++)
            yb[(size_t)(CHUNK * c + j) * CPAIR] = acc[j];

        // Prefetch offsets 8c+38 .. 8c+45 into the slots chunk c retired.
        // l = l0 + 8c + 8 + i: always in [0, LL).
        if (c < NCHUNK - 1) {
#pragma unroll
            for (int i = 0; i < CHUNK; i++) {
                const int off = CHUNK * c + WBUF + i;
                buf[(CHUNK * c + i) % WBUF] = xb[(size_t)(base + off) * CPAIR];
            }
        }
    }
}

extern "C" void kernel_launch(void* const* d_in, const int* in_sizes, int n_in,
                              void* d_out, int out_size) {
    const float* x = (const float*)d_in[0];   // (8, 4096, 16, 128)
    const float* w = (const float*)d_in[1];   // (16, 128, 31)
    float* yv = (float*)d_out;

    dim3 grid(CPAIR / THREADS, LL / TT, BB);  // (16, 32, 8) = 4096 blocks
    _DepthwiseFIRConv1d_kernel<<<grid, THREADS>>>(x, w, yv);
}